// round 11
// baseline (speedup 1.0000x reference)
#include <cuda_runtime.h>
#include <math.h>

#define DD 2048
#define LL 128
#define BB 64
#define NTHR 256
#define WPB (NTHR / 32)          // 8 warps per block -> 8 rows per block
#define NBLK1 (BB * LL / WPB)    // 1024 blocks, one warp per row, no stride

// Scratch (no device allocation allowed)
__device__ float    g_dj[BB * LL];
__device__ float    g_ek[BB * LL];
__device__ float    g_psum[BB];
__device__ int      g_pcnt[BB];
__device__ unsigned g_done;      // monotonic completion counter (replay-safe)

__device__ __forceinline__ float softplus_stable(float x) {
    return fmaxf(x, 0.f) + log1pf(expf(-fabsf(x)));
}

// ---------------------------------------------------------------------------
// Kernel 1: warp-per-row dual dot products. 67 MB HBM stream.
// 4 blocks/SM (64-reg cap) x 8 warps = 32 warps/SM; loads staged 8-deep
// with __ldcs (read-once streaming). No inter-block sync -> no hang mode.
// ---------------------------------------------------------------------------
__global__ __launch_bounds__(NTHR, 4) void rowdot_kernel(
    const float* __restrict__ enc,   // [64,128,2048]
    const float* __restrict__ W)     // [4096,2] row-major
{
    __shared__ float s_wl[DD];
    __shared__ float s_wr[DD];

    const int tid = threadIdx.x;

    // column-diff weight vectors in smem
    for (int d = tid; d < DD; d += NTHR) {
        float2 a = *(const float2*)(W + 2 * d);
        float2 r = *(const float2*)(W + 2 * (DD + d));
        s_wl[d] = a.y - a.x;
        s_wr[d] = r.y - r.x;
    }
    __syncthreads();

    const int warp = tid >> 5;
    const int lane = tid & 31;
    const int row  = blockIdx.x * WPB + warp;          // exact cover, no loop
    const float4* e4  = (const float4*)(enc + (size_t)row * DD);
    const float4* wl4 = (const float4*)s_wl;
    const float4* wr4 = (const float4*)s_wr;

    float sd = 0.f, se = 0.f;
#pragma unroll
    for (int half = 0; half < 2; ++half) {
        float4 e[8];
#pragma unroll
        for (int it = 0; it < 8; ++it)                 // 8 LDG.128 batched
            e[it] = __ldcs(&e4[lane + (half * 8 + it) * 32]);
#pragma unroll
        for (int it = 0; it < 8; ++it) {
            int i = lane + (half * 8 + it) * 32;
            float4 a = wl4[i];
            float4 r = wr4[i];
            sd += e[it].x * a.x + e[it].y * a.y + e[it].z * a.z + e[it].w * a.w;
            se += e[it].x * r.x + e[it].y * r.y + e[it].z * r.z + e[it].w * r.w;
        }
    }
#pragma unroll
    for (int o = 16; o; o >>= 1) {
        sd += __shfl_down_sync(0xFFFFFFFFu, sd, o);
        se += __shfl_down_sync(0xFFFFFFFFu, se, o);
    }
    if (lane == 0) {
        g_dj[row] = sd;
        g_ek[row] = se;
    }
}

// ---------------------------------------------------------------------------
// Kernel 2: one block per batch. Pair softplus sweep; last block finalizes.
// ---------------------------------------------------------------------------
__global__ __launch_bounds__(NTHR) void pair_kernel(
    const int*   __restrict__ mask,  // [64,128]
    const float* __restrict__ bias,  // [2]
    float* __restrict__ out)
{
    __shared__ float s_red[NTHR];
    __shared__ float s_dj[LL];
    __shared__ float s_ek[LL];
    __shared__ int   s_len;

    const int b   = blockIdx.x;
    const int tid = threadIdx.x;

    // turn length = sum(mask[b,:])
    float m = (tid < LL) ? (float)mask[b * LL + tid] : 0.f;
    s_red[tid] = m;
    __syncthreads();
#pragma unroll
    for (int o = NTHR / 2; o; o >>= 1) {
        if (tid < o) s_red[tid] += s_red[tid + o];
        __syncthreads();
    }
    if (tid == 0) s_len = (int)(s_red[0] + 0.5f);

    if (tid < LL) {
        s_dj[tid] = g_dj[b * LL + tid];
        s_ek[tid] = g_ek[b * LL + tid];
    }
    __syncthreads();

    const int   len = s_len;
    const float db  = bias[1] - bias[0];
    float acc = 0.f;
    for (int j = 1; j < len; ++j) {
        float dj = s_dj[j];
        for (int k = tid; k < j; k += NTHR) {
            float x = dj + s_ek[k] + db;
            if (k == j - 1) x = -x;          // label 1 -> softplus(-(z1-z0))
            acc += softplus_stable(x);
        }
    }

    s_red[tid] = acc;
    __syncthreads();
#pragma unroll
    for (int o = NTHR / 2; o; o >>= 1) {
        if (tid < o) s_red[tid] += s_red[tid + o];
        __syncthreads();
    }

    // Deterministic per-batch partials; last-arriving block finalizes.
    if (tid == 0) {
        __stcg(&g_psum[b], s_red[0]);
        __stcg(&g_pcnt[b], len * (len - 1) / 2);
        __threadfence();
        unsigned old = atomicAdd(&g_done, 1u);
        if ((old % (unsigned)BB) == (unsigned)(BB - 1)) {
            __threadfence();
            double s = 0.0;
            int    c = 0;
            for (int i = 0; i < BB; ++i) {
                s += (double)__ldcg(&g_psum[i]);
                c += __ldcg(&g_pcnt[i]);
            }
            if (c < 1) c = 1;
            out[0] = (float)(s / (double)c);
        }
    }
}

extern "C" void kernel_launch(void* const* d_in, const int* in_sizes, int n_in,
                              void* d_out, int out_size) {
    const float* enc  = (const float*)d_in[0];  // [64,128,2048] f32
    const int*   mask = (const int*)d_in[1];    // [64,128] i32
    const float* W    = (const float*)d_in[2];  // [4096,2] f32
    const float* bias = (const float*)d_in[3];  // [2] f32
    float* out = (float*)d_out;

    rowdot_kernel<<<NBLK1, NTHR>>>(enc, W);
    pair_kernel<<<BB, NTHR>>>(mask, bias, out);
}

// round 12
// speedup vs baseline: 1.4054x; 1.4054x over previous
#include <cuda_runtime.h>
#include <math.h>

#define DD 2048
#define LL 128
#define BB 64
#define NTHR 256
#define WPB (NTHR / 32)          // 8 warps per block -> 8 rows per block
#define NBLK1 (BB * LL / WPB)    // 1024 blocks, one warp per row, no stride

// Scratch (no device allocation allowed)
__device__ float    g_dj[BB * LL];
__device__ float    g_ek[BB * LL];
__device__ float    g_psum[BB];
__device__ int      g_pcnt[BB];
__device__ unsigned g_done;      // monotonic completion counter (replay-safe)

// Fast softplus: two MUFU ops (EX2/LG2 via fast intrinsics). |err| ~1e-6,
// tolerance is 1e-3.
__device__ __forceinline__ float softplus_fast(float x) {
    return fmaxf(x, 0.f) + __logf(1.f + __expf(-fabsf(x)));
}

// ---------------------------------------------------------------------------
// Kernel 1 (UNCHANGED — measured ~10us, near HBM roofline): warp-per-row dual
// dot products; 4 blocks/SM x 8 warps = 32 warps/SM; 8-deep staged __ldcs.
// ---------------------------------------------------------------------------
__global__ __launch_bounds__(NTHR, 4) void rowdot_kernel(
    const float* __restrict__ enc,   // [64,128,2048]
    const float* __restrict__ W)     // [4096,2] row-major
{
    __shared__ float s_wl[DD];
    __shared__ float s_wr[DD];

    const int tid = threadIdx.x;

    for (int d = tid; d < DD; d += NTHR) {
        float2 a = *(const float2*)(W + 2 * d);
        float2 r = *(const float2*)(W + 2 * (DD + d));
        s_wl[d] = a.y - a.x;
        s_wr[d] = r.y - r.x;
    }
    __syncthreads();

    const int warp = tid >> 5;
    const int lane = tid & 31;
    const int row  = blockIdx.x * WPB + warp;
    const float4* e4  = (const float4*)(enc + (size_t)row * DD);
    const float4* wl4 = (const float4*)s_wl;
    const float4* wr4 = (const float4*)s_wr;

    float sd = 0.f, se = 0.f;
#pragma unroll
    for (int half = 0; half < 2; ++half) {
        float4 e[8];
#pragma unroll
        for (int it = 0; it < 8; ++it)
            e[it] = __ldcs(&e4[lane + (half * 8 + it) * 32]);
#pragma unroll
        for (int it = 0; it < 8; ++it) {
            int i = lane + (half * 8 + it) * 32;
            float4 a = wl4[i];
            float4 r = wr4[i];
            sd += e[it].x * a.x + e[it].y * a.y + e[it].z * a.z + e[it].w * a.w;
            se += e[it].x * r.x + e[it].y * r.y + e[it].z * r.z + e[it].w * r.w;
        }
    }
#pragma unroll
    for (int o = 16; o; o >>= 1) {
        sd += __shfl_down_sync(0xFFFFFFFFu, sd, o);
        se += __shfl_down_sync(0xFFFFFFFFu, se, o);
    }
    if (lane == 0) {
        g_dj[row] = sd;
        g_ek[row] = se;
    }
}

// ---------------------------------------------------------------------------
// Kernel 2: one block per batch. FLATTENED pair sweep — thread t handles pair
// indices t, t+256, ... of the triangular (j,k) space (k < j < len), decoded
// with float sqrt + integer fix-up. Independent iterations, MUFU softplus.
// ---------------------------------------------------------------------------
__global__ __launch_bounds__(NTHR) void pair_kernel(
    const int*   __restrict__ mask,  // [64,128]
    const float* __restrict__ bias,  // [2]
    float* __restrict__ out)
{
    __shared__ float s_red[NTHR];
    __shared__ float s_dj[LL];
    __shared__ float s_ek[LL];
    __shared__ int   s_len;

    const int b   = blockIdx.x;
    const int tid = threadIdx.x;

    // turn length = sum(mask[b,:]) — warp-level, then one smem word
    if (tid < LL) {
        int v = mask[b * LL + tid];
#pragma unroll
        for (int o = 16; o; o >>= 1)
            v += __shfl_down_sync(0xFFFFFFFFu, v, o);
        if ((tid & 31) == 0) s_red[tid >> 5] = (float)v;
    }
    if (tid < LL) {
        s_dj[tid] = g_dj[b * LL + tid];
        s_ek[tid] = g_ek[b * LL + tid];
    }
    __syncthreads();
    if (tid == 0)
        s_len = (int)(s_red[0] + s_red[1] + s_red[2] + s_red[3] + 0.5f);
    __syncthreads();

    const int   len    = s_len;
    const int   npairs = len * (len - 1) / 2;
    const float db     = bias[1] - bias[0];

    float acc = 0.f;
    for (int idx = tid; idx < npairs; idx += NTHR) {
        // triangular decode: largest j with j*(j-1)/2 <= idx
        int j = (int)((1.0f + sqrtf(1.0f + 8.0f * (float)idx)) * 0.5f);
        // exact fix-up (float sqrt can be off by 1 either way)
        while (j * (j - 1) / 2 > idx) --j;
        while ((j + 1) * j / 2 <= idx) ++j;
        int k = idx - j * (j - 1) / 2;

        float x = s_dj[j] + s_ek[k] + db;
        if (k == j - 1) x = -x;          // label 1 -> softplus(-(z1-z0))
        acc += softplus_fast(x);
    }

    s_red[tid] = acc;
    __syncthreads();
#pragma unroll
    for (int o = NTHR / 2; o; o >>= 1) {
        if (tid < o) s_red[tid] += s_red[tid + o];
        __syncthreads();
    }

    // Deterministic per-batch partials; last-arriving block finalizes.
    if (tid == 0) {
        __stcg(&g_psum[b], s_red[0]);
        __stcg(&g_pcnt[b], npairs);
        __threadfence();
        unsigned old = atomicAdd(&g_done, 1u);
        if ((old % (unsigned)BB) == (unsigned)(BB - 1)) {
            __threadfence();
            double s = 0.0;
            int    c = 0;
            for (int i = 0; i < BB; ++i) {
                s += (double)__ldcg(&g_psum[i]);
                c += __ldcg(&g_pcnt[i]);
            }
            if (c < 1) c = 1;
            out[0] = (float)(s / (double)c);
        }
    }
}

extern "C" void kernel_launch(void* const* d_in, const int* in_sizes, int n_in,
                              void* d_out, int out_size) {
    const float* enc  = (const float*)d_in[0];  // [64,128,2048] f32
    const int*   mask = (const int*)d_in[1];    // [64,128] i32
    const float* W    = (const float*)d_in[2];  // [4096,2] f32
    const float* bias = (const float*)d_in[3];  // [2] f32
    float* out = (float*)d_out;

    rowdot_kernel<<<NBLK1, NTHR>>>(enc, W);
    pair_kernel<<<BB, NTHR>>>(mask, bias, out);
}

// round 13
// speedup vs baseline: 1.4665x; 1.0435x over previous
#include <cuda_runtime.h>
#include <math.h>

#define DD 2048
#define LL 128
#define BB 64
#define NTHR 256
#define WPB (NTHR / 32)          // 8 warps per block -> 8 rows per block
#define NBLK1 (BB * LL / WPB)    // 1024 blocks, one warp per row, no stride

// Scratch (no device allocation allowed)
__device__ float    g_dj[BB * LL];
__device__ float    g_ek[BB * LL];
__device__ float    g_psum[BB];
__device__ int      g_pcnt[BB];
__device__ unsigned g_done;      // monotonic completion counter (replay-safe)

// Fast softplus: two MUFU ops (EX2/LG2 via fast intrinsics). |err| ~1e-6,
// tolerance is 1e-3.
__device__ __forceinline__ float softplus_fast(float x) {
    return fmaxf(x, 0.f) + __logf(1.f + __expf(-fabsf(x)));
}

// ---------------------------------------------------------------------------
// Kernel 1 (UNCHANGED — measured ~10us, near HBM roofline): warp-per-row dual
// dot products; 4 blocks/SM x 8 warps = 32 warps/SM; 8-deep staged __ldcs.
// ---------------------------------------------------------------------------
__global__ __launch_bounds__(NTHR, 4) void rowdot_kernel(
    const float* __restrict__ enc,   // [64,128,2048]
    const float* __restrict__ W)     // [4096,2] row-major
{
    __shared__ float s_wl[DD];
    __shared__ float s_wr[DD];

    const int tid = threadIdx.x;

    for (int d = tid; d < DD; d += NTHR) {
        float2 a = *(const float2*)(W + 2 * d);
        float2 r = *(const float2*)(W + 2 * (DD + d));
        s_wl[d] = a.y - a.x;
        s_wr[d] = r.y - r.x;
    }
    __syncthreads();

    const int warp = tid >> 5;
    const int lane = tid & 31;
    const int row  = blockIdx.x * WPB + warp;
    const float4* e4  = (const float4*)(enc + (size_t)row * DD);
    const float4* wl4 = (const float4*)s_wl;
    const float4* wr4 = (const float4*)s_wr;

    float sd = 0.f, se = 0.f;
#pragma unroll
    for (int half = 0; half < 2; ++half) {
        float4 e[8];
#pragma unroll
        for (int it = 0; it < 8; ++it)
            e[it] = __ldcs(&e4[lane + (half * 8 + it) * 32]);
#pragma unroll
        for (int it = 0; it < 8; ++it) {
            int i = lane + (half * 8 + it) * 32;
            float4 a = wl4[i];
            float4 r = wr4[i];
            sd += e[it].x * a.x + e[it].y * a.y + e[it].z * a.z + e[it].w * a.w;
            se += e[it].x * r.x + e[it].y * r.y + e[it].z * r.z + e[it].w * r.w;
        }
    }
#pragma unroll
    for (int o = 16; o; o >>= 1) {
        sd += __shfl_down_sync(0xFFFFFFFFu, sd, o);
        se += __shfl_down_sync(0xFFFFFFFFu, se, o);
    }
    if (lane == 0) {
        g_dj[row] = sd;
        g_ek[row] = se;
    }
}

// ---------------------------------------------------------------------------
// Kernel 2: one block per batch. FLATTENED pair sweep — thread t handles pair
// indices t, t+256, ... of the triangular (j,k) space (k < j < len), decoded
// with float sqrt + integer fix-up. Independent iterations, MUFU softplus.
// ---------------------------------------------------------------------------
__global__ __launch_bounds__(NTHR) void pair_kernel(
    const int*   __restrict__ mask,  // [64,128]
    const float* __restrict__ bias,  // [2]
    float* __restrict__ out)
{
    __shared__ float s_red[NTHR];
    __shared__ float s_dj[LL];
    __shared__ float s_ek[LL];
    __shared__ int   s_len;

    const int b   = blockIdx.x;
    const int tid = threadIdx.x;

    // turn length = sum(mask[b,:]) — warp-level, then one smem word
    if (tid < LL) {
        int v = mask[b * LL + tid];
#pragma unroll
        for (int o = 16; o; o >>= 1)
            v += __shfl_down_sync(0xFFFFFFFFu, v, o);
        if ((tid & 31) == 0) s_red[tid >> 5] = (float)v;
    }
    if (tid < LL) {
        s_dj[tid] = g_dj[b * LL + tid];
        s_ek[tid] = g_ek[b * LL + tid];
    }
    __syncthreads();
    if (tid == 0)
        s_len = (int)(s_red[0] + s_red[1] + s_red[2] + s_red[3] + 0.5f);
    __syncthreads();

    const int   len    = s_len;
    const int   npairs = len * (len - 1) / 2;
    const float db     = bias[1] - bias[0];

    float acc = 0.f;
    for (int idx = tid; idx < npairs; idx += NTHR) {
        // triangular decode: largest j with j*(j-1)/2 <= idx
        int j = (int)((1.0f + sqrtf(1.0f + 8.0f * (float)idx)) * 0.5f);
        // exact fix-up (float sqrt can be off by 1 either way)
        while (j * (j - 1) / 2 > idx) --j;
        while ((j + 1) * j / 2 <= idx) ++j;
        int k = idx - j * (j - 1) / 2;

        float x = s_dj[j] + s_ek[k] + db;
        if (k == j - 1) x = -x;          // label 1 -> softplus(-(z1-z0))
        acc += softplus_fast(x);
    }

    s_red[tid] = acc;
    __syncthreads();
#pragma unroll
    for (int o = NTHR / 2; o; o >>= 1) {
        if (tid < o) s_red[tid] += s_red[tid + o];
        __syncthreads();
    }

    // Deterministic per-batch partials; last-arriving block finalizes.
    if (tid == 0) {
        __stcg(&g_psum[b], s_red[0]);
        __stcg(&g_pcnt[b], npairs);
        __threadfence();
        unsigned old = atomicAdd(&g_done, 1u);
        if ((old % (unsigned)BB) == (unsigned)(BB - 1)) {
            __threadfence();
            double s = 0.0;
            int    c = 0;
            for (int i = 0; i < BB; ++i) {
                s += (double)__ldcg(&g_psum[i]);
                c += __ldcg(&g_pcnt[i]);
            }
            if (c < 1) c = 1;
            out[0] = (float)(s / (double)c);
        }
    }
}

extern "C" void kernel_launch(void* const* d_in, const int* in_sizes, int n_in,
                              void* d_out, int out_size) {
    const float* enc  = (const float*)d_in[0];  // [64,128,2048] f32
    const int*   mask = (const int*)d_in[1];    // [64,128] i32
    const float* W    = (const float*)d_in[2];  // [4096,2] f32
    const float* bias = (const float*)d_in[3];  // [2] f32
    float* out = (float*)d_out;

    rowdot_kernel<<<NBLK1, NTHR>>>(enc, W);
    pair_kernel<<<BB, NTHR>>>(mask, bias, out);
}

// round 14
// speedup vs baseline: 1.9024x; 1.2973x over previous
#include <cuda_runtime.h>
#include <math.h>

#define DD 2048
#define LL 128
#define BB 64
#define NTHR 256
#define WPB (NTHR / 32)          // 8 warps per block -> 8 rows per block
#define NBLK1 (BB * LL / WPB)    // 1024 blocks, one warp per row
#define SPLIT 8                  // pair-space slices per batch
#define NBLK2 (BB * SPLIT)       // 512 blocks in pair kernel

// Scratch (no device allocation allowed)
__device__ float    g_dj[BB * LL];
__device__ float    g_ek[BB * LL];
__device__ float    g_psum[NBLK2];
__device__ int      g_pcnt[BB];
__device__ unsigned g_done;      // monotonic completion counter (replay-safe)

// Fast softplus: MUFU-based. |err| ~1e-6 vs 1e-3 tolerance.
__device__ __forceinline__ float softplus_fast(float x) {
    return fmaxf(x, 0.f) + __logf(1.f + __expf(-fabsf(x)));
}

// ---------------------------------------------------------------------------
// Kernel 1 (UNCHANGED — ~10us, HBM roofline): warp-per-row dual dot products;
// 4 blocks/SM x 8 warps = 32 warps/SM; 8-deep staged __ldcs.
// ---------------------------------------------------------------------------
__global__ __launch_bounds__(NTHR, 4) void rowdot_kernel(
    const float* __restrict__ enc,   // [64,128,2048]
    const float* __restrict__ W)     // [4096,2] row-major
{
    __shared__ float s_wl[DD];
    __shared__ float s_wr[DD];

    const int tid = threadIdx.x;

    for (int d = tid; d < DD; d += NTHR) {
        float2 a = *(const float2*)(W + 2 * d);
        float2 r = *(const float2*)(W + 2 * (DD + d));
        s_wl[d] = a.y - a.x;
        s_wr[d] = r.y - r.x;
    }
    __syncthreads();

    const int warp = tid >> 5;
    const int lane = tid & 31;
    const int row  = blockIdx.x * WPB + warp;
    const float4* e4  = (const float4*)(enc + (size_t)row * DD);
    const float4* wl4 = (const float4*)s_wl;
    const float4* wr4 = (const float4*)s_wr;

    float sd = 0.f, se = 0.f;
#pragma unroll
    for (int half = 0; half < 2; ++half) {
        float4 e[8];
#pragma unroll
        for (int it = 0; it < 8; ++it)
            e[it] = __ldcs(&e4[lane + (half * 8 + it) * 32]);
#pragma unroll
        for (int it = 0; it < 8; ++it) {
            int i = lane + (half * 8 + it) * 32;
            float4 a = wl4[i];
            float4 r = wr4[i];
            sd += e[it].x * a.x + e[it].y * a.y + e[it].z * a.z + e[it].w * a.w;
            se += e[it].x * r.x + e[it].y * r.y + e[it].z * r.z + e[it].w * r.w;
        }
    }
#pragma unroll
    for (int o = 16; o; o >>= 1) {
        sd += __shfl_down_sync(0xFFFFFFFFu, sd, o);
        se += __shfl_down_sync(0xFFFFFFFFu, se, o);
    }
    if (lane == 0) {
        g_dj[row] = sd;
        g_ek[row] = se;
    }
}

// ---------------------------------------------------------------------------
// Kernel 2: 64 batches x 8 slices = 512 blocks. Each block sweeps 1/8 of its
// batch's flattened triangular pair space (<=4 iters/thread). Last-arriving
// block does a parallel tree-reduce of all 512 partials + 64 counts.
// ---------------------------------------------------------------------------
__global__ __launch_bounds__(NTHR) void pair_kernel(
    const int*   __restrict__ mask,  // [64,128]
    const float* __restrict__ bias,  // [2]
    float* __restrict__ out)
{
    __shared__ float s_red[NTHR];
    __shared__ float s_dj[LL];
    __shared__ float s_ek[LL];
    __shared__ int   s_len;
    __shared__ int   s_last;
    __shared__ float s_fin[NBLK2 / 2];   // 256 — final tree-reduce scratch

    const int blk   = blockIdx.x;
    const int b     = blk >> 3;          // batch
    const int slice = blk & (SPLIT - 1);
    const int tid   = threadIdx.x;

    // turn length = sum(mask[b,:]) — warp reduce, 4 partials
    if (tid < LL) {
        int v = mask[b * LL + tid];
#pragma unroll
        for (int o = 16; o; o >>= 1)
            v += __shfl_down_sync(0xFFFFFFFFu, v, o);
        if ((tid & 31) == 0) s_red[tid >> 5] = (float)v;
    }
    if (tid < LL) {
        s_dj[tid] = g_dj[b * LL + tid];
        s_ek[tid] = g_ek[b * LL + tid];
    }
    __syncthreads();
    if (tid == 0)
        s_len = (int)(s_red[0] + s_red[1] + s_red[2] + s_red[3] + 0.5f);
    __syncthreads();

    const int   len    = s_len;
    const int   npairs = len * (len - 1) / 2;
    const float db     = bias[1] - bias[0];

    float acc = 0.f;
    for (int idx = slice * NTHR + tid; idx < npairs; idx += NTHR * SPLIT) {
        int j = (int)((1.0f + sqrtf(1.0f + 8.0f * (float)idx)) * 0.5f);
        while (j * (j - 1) / 2 > idx) --j;
        while ((j + 1) * j / 2 <= idx) ++j;
        int k = idx - j * (j - 1) / 2;

        float x = s_dj[j] + s_ek[k] + db;
        if (k == j - 1) x = -x;          // label 1 -> softplus(-(z1-z0))
        acc += softplus_fast(x);
    }

    s_red[tid] = acc;
    __syncthreads();
#pragma unroll
    for (int o = NTHR / 2; o; o >>= 1) {
        if (tid < o) s_red[tid] += s_red[tid + o];
        __syncthreads();
    }

    // Publish partial; detect last-arriving block (monotonic, replay-safe).
    if (tid == 0) {
        __stcg(&g_psum[blk], s_red[0]);
        if (slice == 0) __stcg(&g_pcnt[b], npairs);
        __threadfence();
        unsigned old = atomicAdd(&g_done, 1u);
        s_last = ((old % (unsigned)NBLK2) == (unsigned)(NBLK2 - 1));
    }
    __syncthreads();

    // Last block: parallel deterministic tree-reduce of 512 partials.
    if (s_last) {
        __threadfence();
        float v = __ldcg(&g_psum[tid]) + __ldcg(&g_psum[tid + NTHR]);
        s_fin[tid] = v;
        int c = (tid < BB) ? __ldcg(&g_pcnt[tid]) : 0;
        __syncthreads();
#pragma unroll
        for (int o = NTHR / 2; o; o >>= 1) {
            if (tid < o) s_fin[tid] += s_fin[tid + o];
            __syncthreads();
        }
#pragma unroll
        for (int o = 16; o; o >>= 1)
            c += __shfl_down_sync(0xFFFFFFFFu, c, o);
        if (tid < BB && (tid & 31) == 0) s_red[tid >> 5] = (float)c;
        __syncthreads();
        if (tid == 0) {
            int cnt = (int)(s_red[0] + s_red[1] + 0.5f);
            if (cnt < 1) cnt = 1;
            out[0] = s_fin[0] / (float)cnt;
        }
    }
}

extern "C" void kernel_launch(void* const* d_in, const int* in_sizes, int n_in,
                              void* d_out, int out_size) {
    const float* enc  = (const float*)d_in[0];  // [64,128,2048] f32
    const int*   mask = (const int*)d_in[1];    // [64,128] i32
    const float* W    = (const float*)d_in[2];  // [4096,2] f32
    const float* bias = (const float*)d_in[3];  // [2] f32
    float* out = (float*)d_out;

    rowdot_kernel<<<NBLK1, NTHR>>>(enc, W);
    pair_kernel<<<NBLK2, NTHR>>>(mask, bias, out);
}